// round 16
// baseline (speedup 1.0000x reference)
#include <cuda_runtime.h>
#include <cuda_fp16.h>
#include <cstdint>

#define B_DIM 8192
#define I_DIM 512
#define C_DIM 2048

#define BM 128
#define BN 128
#define BK 32                        // K-slice of x per iteration
#define NITER (I_DIM / BK)           // 16
#define NSTAGE 3
#define PITCH 40                     // halves per smem row (32 + 8 pad) = 80 B (16B-aligned)
#define REGION_BYTES (BM * PITCH * 2)        // 10240 (one operand tile)
#define STAGE_BYTES (3 * REGION_BYTES)       // 30720 (A + B1 + B2)
#define SMEM_BYTES (NSTAGE * STAGE_BYTES)    // 92160

// ---------------- device scratch (no allocs allowed) ----------------
__device__ __half g_a [B_DIM * I_DIM];   // h(x)                    (8192, 512)
__device__ __half g_bt[C_DIM * 1024];    // [h(w^2) | h(-2 w^2 c)]  (2048, 1024)
__device__ float  g_t3p[16 * C_DIM];
__device__ float  g_t3[C_DIM];

// ---------------- helpers ----------------
__device__ __forceinline__ uint32_t smem_u32(const void* p) {
    uint32_t a;
    asm("{ .reg .u64 t; cvta.to.shared.u64 t, %1; cvt.u32.u64 %0, t; }" : "=r"(a) : "l"(p));
    return a;
}
__device__ __forceinline__ void cp_async16(uint32_t saddr, const void* gaddr) {
    asm volatile("cp.async.cg.shared.global [%0], [%1], 16;" :: "r"(saddr), "l"(gaddr));
}
__device__ __forceinline__ void cp_commit() {
    asm volatile("cp.async.commit_group;" ::: "memory");
}
__device__ __forceinline__ void cp_wait1() {
    asm volatile("cp.async.wait_group 1;" ::: "memory");
}
__device__ __forceinline__ void cp_wait0() {
    asm volatile("cp.async.wait_group 0;" ::: "memory");
}
__device__ __forceinline__ void ldsm_x4(uint32_t* r, uint32_t addr) {
    asm volatile("ldmatrix.sync.aligned.m8n8.x4.shared.b16 {%0,%1,%2,%3}, [%4];"
                 : "=r"(r[0]), "=r"(r[1]), "=r"(r[2]), "=r"(r[3]) : "r"(addr));
}
__device__ __forceinline__ uint32_t h2sq(uint32_t v) {
    uint32_t r; asm("mul.rn.f16x2 %0, %1, %1;" : "=r"(r) : "r"(v)); return r;
}
// f16-accumulate MMA: D (f16x2 x2) = A*B + C, C==D registers
__device__ __forceinline__ void mma_h(uint32_t* d, const uint32_t* a, uint32_t b0, uint32_t b1) {
    asm volatile(
        "mma.sync.aligned.m16n8k16.row.col.f16.f16.f16.f16 "
        "{%0,%1}, {%2,%3,%4,%5}, {%6,%7}, {%0,%1};"
        : "+r"(d[0]), "+r"(d[1])
        : "r"(a[0]), "r"(a[1]), "r"(a[2]), "r"(a[3]), "r"(b0), "r"(b1));
}
__device__ __forceinline__ void promote4(float* a, uint32_t d0, uint32_t d1) {
    __half2 h0 = *reinterpret_cast<__half2*>(&d0);
    __half2 h1 = *reinterpret_cast<__half2*>(&d1);
    a[0] += __low2float(h0);  a[1] += __high2float(h0);
    a[2] += __low2float(h1);  a[3] += __high2float(h1);
}

// ---------------------------------------------------------------------------
// prep_w: g_bt[c] = [h(w^2) | h(-2 w^2 centers)], + fp32 t3 partials.
// ---------------------------------------------------------------------------
__global__ void prep_w_kernel(const float* __restrict__ weight,
                              const float* __restrict__ centers) {
    __shared__ float sW[32][33];
    __shared__ float sC[32][33];

    const int i0 = blockIdx.x * 32;
    const int c0 = blockIdx.y * 32;
    const int tx = threadIdx.x;
    const int ty = threadIdx.y;

    #pragma unroll
    for (int ii = ty; ii < 32; ii += 8)
        sW[ii][tx] = weight[(i0 + ii) * C_DIM + c0 + tx];
    #pragma unroll
    for (int cc = ty; cc < 32; cc += 8)
        sC[cc][tx] = centers[(c0 + cc) * I_DIM + i0 + tx];
    __syncthreads();

    #pragma unroll
    for (int cc = ty; cc < 32; cc += 8) {
        float w  = sW[tx][cc];
        float w2 = w * w;
        float ce = sC[cc][tx];
        __half* row = g_bt + (size_t)(c0 + cc) * 1024;
        row[i0 + tx]         = __float2half_rn(w2);
        row[I_DIM + i0 + tx] = __float2half_rn(-2.0f * w2 * ce);
        float v = w2 * ce * ce;
        #pragma unroll
        for (int d = 16; d > 0; d >>= 1)
            v += __shfl_xor_sync(0xFFFFFFFF, v, d);
        if (tx == 0) g_t3p[blockIdx.x * C_DIM + c0 + cc] = v;
    }
}

__global__ void t3_reduce_kernel() {
    int c = blockIdx.x * blockDim.x + threadIdx.x;
    if (c < C_DIM) {
        float s = 0.0f;
        #pragma unroll
        for (int p = 0; p < 16; p++) s += g_t3p[p * C_DIM + c];
        g_t3[c] = s;
    }
}

// ---------------------------------------------------------------------------
// prep_x: g_a = h(x) (x^2 formed in registers inside the GEMM).
// ---------------------------------------------------------------------------
__global__ void prep_x_kernel(const float* __restrict__ x) {
    int f = blockIdx.x * blockDim.x + threadIdx.x;
    int r  = f >> 7;
    int c4 = (f & 127) << 2;
    float4 v = *reinterpret_cast<const float4*>(x + (size_t)r * I_DIM + c4);
    __half2 rw0 = __floats2half2_rn(v.x, v.y);
    __half2 rw1 = __floats2half2_rn(v.z, v.w);
    __half2* pa = reinterpret_cast<__half2*>(g_a + (size_t)r * I_DIM + c4);
    pa[0] = rw0; pa[1] = rw1;
}

// ---------------------------------------------------------------------------
// GEMM: out[b,c] = sum_k x^2 B1 + x B2 + t3, K=512.  f16-ACCUMULATE MMAs in
// k32 windows, promoted to fp32 master accumulators per np-group.
// 128x128x32 iter tile, 3-stage cp.async, 8 warps (4m x 2n), warp 32x64.
// ---------------------------------------------------------------------------
__global__ __launch_bounds__(256, 2)
void rbf_mma_gemm(float* __restrict__ out) {
    extern __shared__ char smem[];
    const uint32_t sbase = smem_u32(smem);

    const int tid = threadIdx.x;
    const int wid = tid >> 5;
    const int lid = tid & 31;
    const int g   = lid >> 2;
    const int tg  = lid & 3;
    const int wm  = wid >> 1;       // 0..3 -> m offset wm*32
    const int wn  = wid & 1;        // 0..1 -> n offset wn*64

    const int block_row = blockIdx.y * BM;
    const int block_col = blockIdx.x * BN;
    const __half* gA = g_a  + (size_t)block_row * I_DIM;
    const __half* gB = g_bt + (size_t)block_col * 1024;

    auto prefetch = [&](int it) {
        const int s  = it % NSTAGE;
        const int k0 = it * BK;
        const uint32_t sa = sbase + s * STAGE_BYTES;
        #pragma unroll
        for (int i = 0; i < 2; i++) {
            const int f   = tid + i * 256;     // [0, 512)
            const int row = f >> 2;            // 0..127
            const int kc  = (f & 3) << 3;      // 0,8,16,24 halves
            const uint32_t soff = (uint32_t)(row * PITCH + kc) * 2;
            cp_async16(sa + soff,
                       gA + (size_t)row * I_DIM + k0 + kc);
            cp_async16(sa + REGION_BYTES + soff,
                       gB + (size_t)row * 1024 + k0 + kc);
            cp_async16(sa + 2 * REGION_BYTES + soff,
                       gB + (size_t)row * 1024 + I_DIM + k0 + kc);
        }
    };

    // ldmatrix per-lane address components
    const int a_row = (lid & 15);
    const int a_kh  = (lid >> 4) << 3;
    const int b_row = (lid & 7) + ((lid & 16) >> 1);
    const int b_kh  = (lid & 8);
    const uint32_t a_lane_off = ((uint32_t)(wm * 32 + a_row) * PITCH + a_kh) * 2;
    const uint32_t b_lane_off = ((uint32_t)(wn * 64 + b_row) * PITCH + b_kh) * 2;

    float acc[2][8][4];
    #pragma unroll
    for (int mf = 0; mf < 2; mf++)
        #pragma unroll
        for (int nf = 0; nf < 8; nf++)
            #pragma unroll
            for (int e = 0; e < 4; e++) acc[mf][nf][e] = 0.0f;

    prefetch(0); cp_commit();
    prefetch(1); cp_commit();

    for (int it = 0; it < NITER; it++) {
        if (it == NITER - 1) cp_wait0(); else cp_wait1();
        __syncthreads();
        if (it + 2 < NITER) { prefetch(it + 2); cp_commit(); }

        const uint32_t stageBase = sbase + (it % NSTAGE) * STAGE_BYTES;
        const uint32_t aBase  = stageBase + a_lane_off;
        const uint32_t b1Base = stageBase + REGION_BYTES + b_lane_off;
        const uint32_t b2Base = stageBase + 2 * REGION_BYTES + b_lane_off;

        // preload A fragments for BOTH k16 slices, square in registers
        uint32_t af[2][2][4], aq[2][2][4];   // [kf][mf][4]
        #pragma unroll
        for (int kf = 0; kf < 2; kf++)
            #pragma unroll
            for (int mf = 0; mf < 2; mf++) {
                ldsm_x4(af[kf][mf],
                        aBase + (uint32_t)(mf * 16 * PITCH) * 2 + (uint32_t)(kf * 16) * 2);
                #pragma unroll
                for (int e = 0; e < 4; e++) aq[kf][mf][e] = h2sq(af[kf][mf][e]);
            }

        #pragma unroll
        for (int np = 0; np < 4; np++) {
            uint32_t b1[2][4], b2[2][4];     // [kf][4]
            #pragma unroll
            for (int kf = 0; kf < 2; kf++) {
                const uint32_t nroff =
                    (uint32_t)(np * 16 * PITCH) * 2 + (uint32_t)(kf * 16) * 2;
                ldsm_x4(b1[kf], b1Base + nroff);
                ldsm_x4(b2[kf], b2Base + nroff);
            }
            // f16 window accumulators: [mf][nf-half][2 regs]
            uint32_t fa[2][2][2];
            #pragma unroll
            for (int mf = 0; mf < 2; mf++)
                #pragma unroll
                for (int h = 0; h < 2; h++) { fa[mf][h][0] = 0u; fa[mf][h][1] = 0u; }

            #pragma unroll
            for (int kf = 0; kf < 2; kf++)
                #pragma unroll
                for (int mf = 0; mf < 2; mf++) {
                    mma_h(fa[mf][0], aq[kf][mf], b1[kf][0], b1[kf][1]);
                    mma_h(fa[mf][0], af[kf][mf], b2[kf][0], b2[kf][1]);
                    mma_h(fa[mf][1], aq[kf][mf], b1[kf][2], b1[kf][3]);
                    mma_h(fa[mf][1], af[kf][mf], b2[kf][2], b2[kf][3]);
                }

            #pragma unroll
            for (int mf = 0; mf < 2; mf++) {
                promote4(acc[mf][np * 2 + 0], fa[mf][0][0], fa[mf][0][1]);
                promote4(acc[mf][np * 2 + 1], fa[mf][1][0], fa[mf][1][1]);
            }
        }
    }

    // ---- epilogue: direct float2 stores + t3 ----
    #pragma unroll
    for (int mf = 0; mf < 2; mf++) {
        const int row0 = block_row + wm * 32 + mf * 16 + g;
        #pragma unroll
        for (int nf = 0; nf < 8; nf++) {
            const int col = block_col + wn * 64 + nf * 8 + tg * 2;
            const float t0 = g_t3[col];
            const float t1 = g_t3[col + 1];
            float2 v0 = make_float2(acc[mf][nf][0] + t0, acc[mf][nf][1] + t1);
            float2 v1 = make_float2(acc[mf][nf][2] + t0, acc[mf][nf][3] + t1);
            *reinterpret_cast<float2*>(out + (size_t)row0 * C_DIM + col)       = v0;
            *reinterpret_cast<float2*>(out + (size_t)(row0 + 8) * C_DIM + col) = v1;
        }
    }
}

// ---------------------------------------------------------------------------
extern "C" void kernel_launch(void* const* d_in, const int* in_sizes, int n_in,
                              void* d_out, int out_size) {
    const float* x       = (const float*)d_in[0];   // (8192, 512)
    const float* weight  = (const float*)d_in[1];   // (512, 2048)
    const float* centers = (const float*)d_in[2];   // (2048, 512)
    float* out = (float*)d_out;                     // (8192, 2048)

    cudaFuncSetAttribute(rbf_mma_gemm, cudaFuncAttributeMaxDynamicSharedMemorySize,
                         SMEM_BYTES);

    dim3 pgrid(I_DIM / 32, C_DIM / 32);
    prep_w_kernel<<<pgrid, dim3(32, 8)>>>(weight, centers);
    t3_reduce_kernel<<<(C_DIM + 255) / 256, 256>>>();
    prep_x_kernel<<<(B_DIM * I_DIM / 4) / 256, 256>>>(x);

    dim3 ggrid(C_DIM / BN, B_DIM / BM);   // (16, 64)
    rbf_mma_gemm<<<ggrid, 256, SMEM_BYTES>>>(out);
}

// round 17
// speedup vs baseline: 1.1667x; 1.1667x over previous
#include <cuda_runtime.h>
#include <cuda_fp16.h>
#include <cstdint>

#define B_DIM 8192
#define I_DIM 512
#define C_DIM 2048
#define K_TOT 1024          // concatenated K: [x^2 | x]

#define BM 128
#define BN 128
#define BK 64
#define NITER (K_TOT / BK)          // 16
#define NSTAGE 3
#define ROW_PITCH_H 72              // halves per smem row (64 + 8 pad) = 144 B
#define STAGE_A_BYTES (BM * ROW_PITCH_H * 2)       // 18432
#define STAGE_BYTES (2 * STAGE_A_BYTES)            // 36864 (A + B)

// ---------------- device scratch (no allocs allowed) ----------------
__device__ __half g_a [B_DIM * K_TOT];   // [h(x^2) | h(x)]            (8192, 1024)
__device__ __half g_bt[C_DIM * K_TOT];   // [h(w^2) | h(-2 w^2 c)]     (2048, 1024)
__device__ float  g_t3p[16 * C_DIM];
__device__ float  g_t3[C_DIM];

// ---------------- helpers ----------------
__device__ __forceinline__ uint32_t smem_u32(const void* p) {
    uint32_t a;
    asm("{ .reg .u64 t; cvta.to.shared.u64 t, %1; cvt.u32.u64 %0, t; }" : "=r"(a) : "l"(p));
    return a;
}
__device__ __forceinline__ void cp_async16(uint32_t saddr, const void* gaddr) {
    asm volatile("cp.async.cg.shared.global [%0], [%1], 16;" :: "r"(saddr), "l"(gaddr));
}
__device__ __forceinline__ void cp_commit() {
    asm volatile("cp.async.commit_group;" ::: "memory");
}
__device__ __forceinline__ void cp_wait1() {
    asm volatile("cp.async.wait_group 1;" ::: "memory");
}
__device__ __forceinline__ void cp_wait0() {
    asm volatile("cp.async.wait_group 0;" ::: "memory");
}
__device__ __forceinline__ void ldsm_x4(uint32_t* r, uint32_t addr) {
    asm volatile("ldmatrix.sync.aligned.m8n8.x4.shared.b16 {%0,%1,%2,%3}, [%4];"
                 : "=r"(r[0]), "=r"(r[1]), "=r"(r[2]), "=r"(r[3]) : "r"(addr));
}
__device__ __forceinline__ void mma_f16(float* d, const uint32_t* a, uint32_t b0, uint32_t b1) {
    asm volatile(
        "mma.sync.aligned.m16n8k16.row.col.f32.f16.f16.f32 "
        "{%0,%1,%2,%3}, {%4,%5,%6,%7}, {%8,%9}, {%0,%1,%2,%3};"
        : "+f"(d[0]), "+f"(d[1]), "+f"(d[2]), "+f"(d[3])
        : "r"(a[0]), "r"(a[1]), "r"(a[2]), "r"(a[3]), "r"(b0), "r"(b1));
}

// ---------------------------------------------------------------------------
// prep_w: g_bt[c][k] = h(w^2) | h(-2 w^2 centers), + fp32 t3 partials.
// ---------------------------------------------------------------------------
__global__ void prep_w_kernel(const float* __restrict__ weight,
                              const float* __restrict__ centers) {
    __shared__ float sW[32][33];
    __shared__ float sC[32][33];

    const int i0 = blockIdx.x * 32;
    const int c0 = blockIdx.y * 32;
    const int tx = threadIdx.x;
    const int ty = threadIdx.y;

    #pragma unroll
    for (int ii = ty; ii < 32; ii += 8)
        sW[ii][tx] = weight[(i0 + ii) * C_DIM + c0 + tx];
    #pragma unroll
    for (int cc = ty; cc < 32; cc += 8)
        sC[cc][tx] = centers[(c0 + cc) * I_DIM + i0 + tx];
    __syncthreads();

    #pragma unroll
    for (int cc = ty; cc < 32; cc += 8) {
        float w  = sW[tx][cc];
        float w2 = w * w;
        float ce = sC[cc][tx];
        __half* row = g_bt + (size_t)(c0 + cc) * K_TOT;
        row[i0 + tx]         = __float2half_rn(w2);
        row[I_DIM + i0 + tx] = __float2half_rn(-2.0f * w2 * ce);
        float v = w2 * ce * ce;
        #pragma unroll
        for (int d = 16; d > 0; d >>= 1)
            v += __shfl_xor_sync(0xFFFFFFFF, v, d);
        if (tx == 0) g_t3p[blockIdx.x * C_DIM + c0 + cc] = v;
    }
}

// ---------------------------------------------------------------------------
// prep_x: g_a[b][0:512] = h(x^2), g_a[b][512:1024] = h(x).
// FUSED t3 reduction: blocks 0..7 each reduce 256 t3 columns (prep_w
// precedes this kernel in stream order, so g_t3p is complete).
// ---------------------------------------------------------------------------
__global__ void prep_x_kernel(const float* __restrict__ x) {
    int f = blockIdx.x * blockDim.x + threadIdx.x;
    int r  = f >> 7;
    int c4 = (f & 127) << 2;
    float4 v = *reinterpret_cast<const float4*>(x + (size_t)r * I_DIM + c4);
    __half2 sq0 = __floats2half2_rn(v.x * v.x, v.y * v.y);
    __half2 sq1 = __floats2half2_rn(v.z * v.z, v.w * v.w);
    __half2 rw0 = __floats2half2_rn(v.x, v.y);
    __half2 rw1 = __floats2half2_rn(v.z, v.w);
    __half2* pa = reinterpret_cast<__half2*>(g_a + (size_t)r * K_TOT + c4);
    __half2* pb = reinterpret_cast<__half2*>(g_a + (size_t)r * K_TOT + I_DIM + c4);
    pa[0] = sq0; pa[1] = sq1;
    pb[0] = rw0; pb[1] = rw1;

    if (blockIdx.x < 8) {
        int c = blockIdx.x * 256 + threadIdx.x;   // 8 * 256 = 2048 = C_DIM
        float s = 0.0f;
        #pragma unroll
        for (int p = 0; p < 16; p++) s += g_t3p[p * C_DIM + c];
        g_t3[c] = s;
    }
}

// ---------------------------------------------------------------------------
// GEMM (round-5 verbatim): out = g_a @ g_bt^T + t3.  128x128x64 tiles,
// 3-stage cp.async, 8 warps (4m x 2n), warp tile 32x64, m16n8k16 f16/fp32,
// software-pipelined ldmatrix fragments, ONE barrier per k-iteration.
// ---------------------------------------------------------------------------
__global__ __launch_bounds__(256, 2)
void rbf_mma_gemm(float* __restrict__ out) {
    extern __shared__ char smem[];
    const uint32_t sbase = smem_u32(smem);

    const int tid = threadIdx.x;
    const int wid = tid >> 5;
    const int lid = tid & 31;
    const int g   = lid >> 2;
    const int tg  = lid & 3;
    const int wm  = wid >> 1;       // 0..3 -> m offset wm*32
    const int wn  = wid & 1;        // 0..1 -> n offset wn*64

    const int block_row = blockIdx.y * BM;
    const int block_col = blockIdx.x * BN;
    const __half* gA = g_a  + (size_t)block_row * K_TOT;
    const __half* gB = g_bt + (size_t)block_col * K_TOT;

    auto prefetch = [&](int it) {
        const int s  = it % NSTAGE;
        const int k0 = it * BK;
        const uint32_t sa = sbase + s * STAGE_BYTES;
        #pragma unroll
        for (int i = 0; i < 4; i++) {
            int f   = tid + i * 256;
            int row = f >> 3;
            int kc  = (f & 7) << 3;
            uint32_t soff = (uint32_t)(row * ROW_PITCH_H + kc) * 2;
            cp_async16(sa + soff, gA + (size_t)row * K_TOT + k0 + kc);
            cp_async16(sa + STAGE_A_BYTES + soff, gB + (size_t)row * K_TOT + k0 + kc);
        }
    };

    // ldmatrix per-lane address components
    const int a_row = (lid & 15);
    const int a_kh  = (lid >> 4) << 3;
    const int b_row = (lid & 7) + ((lid & 16) >> 1);
    const int b_kh  = (lid & 8);
    const uint32_t a_lane_off = ((uint32_t)(wm * 32 + a_row) * ROW_PITCH_H + a_kh) * 2;
    const uint32_t b_lane_off = ((uint32_t)(wn * 64 + b_row) * ROW_PITCH_H + b_kh) * 2;

    float acc[2][8][4];
    #pragma unroll
    for (int mf = 0; mf < 2; mf++)
        #pragma unroll
        for (int nf = 0; nf < 8; nf++)
            #pragma unroll
            for (int e = 0; e < 4; e++) acc[mf][nf][e] = 0.0f;

    prefetch(0); cp_commit();
    prefetch(1); cp_commit();

    for (int it = 0; it < NITER; it++) {
        if (it == NITER - 1) cp_wait0(); else cp_wait1();
        __syncthreads();
        if (it + 2 < NITER) { prefetch(it + 2); cp_commit(); }

        const uint32_t stageBase = sbase + (it % NSTAGE) * STAGE_BYTES;
        const uint32_t aBase = stageBase + a_lane_off;
        const uint32_t bBase = stageBase + STAGE_A_BYTES + b_lane_off;

        // rotated fragment buffers
        uint32_t afr[2][2][4];   // [kf&1][mf][4]
        uint32_t bfr[2][4];      // [np&1][4]

        ldsm_x4(afr[0][0], aBase);
        ldsm_x4(afr[0][1], aBase + (uint32_t)(16 * ROW_PITCH_H) * 2);
        ldsm_x4(bfr[0],    bBase);

        #pragma unroll
        for (int kf = 0; kf < 4; kf++) {
            #pragma unroll
            for (int np = 0; np < 4; np++) {
                if (!(kf == 3 && np == 3)) {
                    const int nkf = (np == 3) ? kf + 1 : kf;
                    const int nnp = (np == 3) ? 0 : np + 1;
                    ldsm_x4(bfr[(np + 1) & 1],
                            bBase + ((uint32_t)(nnp * 16) * ROW_PITCH_H +
                                     (uint32_t)(nkf * 16)) * 2);
                }
                if (np == 2 && kf < 3) {
                    const uint32_t nakoff = (uint32_t)((kf + 1) * 16) * 2;
                    ldsm_x4(afr[(kf + 1) & 1][0], aBase + nakoff);
                    ldsm_x4(afr[(kf + 1) & 1][1],
                            aBase + (uint32_t)(16 * ROW_PITCH_H) * 2 + nakoff);
                }
                const uint32_t* a0 = afr[kf & 1][0];
                const uint32_t* a1 = afr[kf & 1][1];
                const uint32_t* b  = bfr[np & 1];
                mma_f16(acc[0][np * 2 + 0], a0, b[0], b[1]);
                mma_f16(acc[1][np * 2 + 0], a1, b[0], b[1]);
                mma_f16(acc[0][np * 2 + 1], a0, b[2], b[3]);
                mma_f16(acc[1][np * 2 + 1], a1, b[2], b[3]);
            }
        }
    }

    // ---- epilogue: direct float2 stores + t3 ----
    #pragma unroll
    for (int mf = 0; mf < 2; mf++) {
        const int row0 = block_row + wm * 32 + mf * 16 + g;
        #pragma unroll
        for (int nf = 0; nf < 8; nf++) {
            const int col = block_col + wn * 64 + nf * 8 + tg * 2;
            const float t0 = g_t3[col];
            const float t1 = g_t3[col + 1];
            float2 v0 = make_float2(acc[mf][nf][0] + t0, acc[mf][nf][1] + t1);
            float2 v1 = make_float2(acc[mf][nf][2] + t0, acc[mf][nf][3] + t1);
            *reinterpret_cast<float2*>(out + (size_t)row0 * C_DIM + col)       = v0;
            *reinterpret_cast<float2*>(out + (size_t)(row0 + 8) * C_DIM + col) = v1;
        }
    }
}

// ---------------------------------------------------------------------------
extern "C" void kernel_launch(void* const* d_in, const int* in_sizes, int n_in,
                              void* d_out, int out_size) {
    const float* x       = (const float*)d_in[0];   // (8192, 512)
    const float* weight  = (const float*)d_in[1];   // (512, 2048)
    const float* centers = (const float*)d_in[2];   // (2048, 512)
    float* out = (float*)d_out;                     // (8192, 2048)

    cudaFuncSetAttribute(rbf_mma_gemm, cudaFuncAttributeMaxDynamicSharedMemorySize,
                         NSTAGE * STAGE_BYTES);

    dim3 pgrid(I_DIM / 32, C_DIM / 32);
    prep_w_kernel<<<pgrid, dim3(32, 8)>>>(weight, centers);
    prep_x_kernel<<<(B_DIM * I_DIM / 4) / 256, 256>>>(x);   // t3 reduce fused in

    dim3 ggrid(C_DIM / BN, B_DIM / BM);   // (16, 64)
    rbf_mma_gemm<<<ggrid, 256, NSTAGE * STAGE_BYTES>>>(out);
}